// round 2
// baseline (speedup 1.0000x reference)
#include <cuda_runtime.h>

// ToHeteroLinear: out[i] = x[i] @ W[type[i]] + b[type[i]]
// N=131072, T=16, D_IN=D_OUT=128, fp32. type_vec is SORTED.
//
// Strategy: 128x128 output tile per block. Since types are sorted, almost all
// tiles are single-type -> plain register-blocked SGEMM vs W[t]. Tiles that
// straddle a type boundary (<= 15 of 1024) re-run the GEMM per segment and
// write only the segment's rows.

#define BM 128
#define BN 128
#define BK 32
#define TM 8
#define TN 8
#define NTHREADS 256   // (BM/TM)*(BN/TN)

__global__ __launch_bounds__(NTHREADS, 2)
void hetero_linear_kernel(const float* __restrict__ x,
                          const int* __restrict__ type_vec,
                          const float* __restrict__ weight,
                          const float* __restrict__ bias,
                          float* __restrict__ out,
                          int n_rows)
{
    __shared__ __align__(16) float As[BK][BM + 4];  // x tile, k-major (pad vs conflicts)
    __shared__ __align__(16) float Bs[BK][BN];      // W tile, k-major (natural layout)
    __shared__ int s_types[BM];

    const int r0  = blockIdx.x * BM;
    const int tid = threadIdx.x;

    // Stage the tile's type ids (sorted).
    if (tid < BM) {
        int r = r0 + tid;
        s_types[tid] = (r < n_rows) ? type_vec[r] : -1;
    }
    __syncthreads();

    const int tx = tid & 15;   // output-column group
    const int ty = tid >> 4;   // output-row group

    // Iterate contiguous same-type segments within the 128-row tile.
    // The scan is uniform across all threads (reads smem only), so the
    // __syncthreads() inside the loop body is safe.
    int s0 = 0;
    while (s0 < BM) {
        const int t = s_types[s0];
        int s1 = s0 + 1;
        while (s1 < BM && s_types[s1] == t) s1++;
        if (t < 0) break;  // tail guard (not hit: N % 128 == 0)

        const float* __restrict__ W = weight + (size_t)t * (128 * 128);

        float acc[TM][TN];
        #pragma unroll
        for (int i = 0; i < TM; i++)
            #pragma unroll
            for (int j = 0; j < TN; j++)
                acc[i][j] = 0.0f;

        // ---- Mainloop over K in chunks of BK=32 ----
        #pragma unroll
        for (int kt = 0; kt < 128; kt += BK) {
            // Load x tile [BM rows][BK cols] -> As[k][m] (transposed store).
            // 1024 float4 total, 4 per thread, coalesced global reads.
            #pragma unroll
            for (int it = 0; it < 4; it++) {
                int idx = tid + it * NTHREADS;      // 0..1023
                int m   = idx >> 3;                 // row in tile (0..127)
                int k4  = (idx & 7) << 2;           // k offset (0,4,..,28)
                float4 v = *reinterpret_cast<const float4*>(
                    &x[(size_t)(r0 + m) * 128 + kt + k4]);
                As[k4 + 0][m] = v.x;
                As[k4 + 1][m] = v.y;
                As[k4 + 2][m] = v.z;
                As[k4 + 3][m] = v.w;
            }
            // Load W tile [BK rows][BN cols] -> Bs (direct, coalesced float4).
            #pragma unroll
            for (int it = 0; it < 4; it++) {
                int idx = tid + it * NTHREADS;      // 0..1023
                int k   = idx >> 5;                 // 0..31
                int n4  = (idx & 31) << 2;          // 0,4,...,124
                *reinterpret_cast<float4*>(&Bs[k][n4]) =
                    *reinterpret_cast<const float4*>(&W[(size_t)(kt + k) * 128 + n4]);
            }
            __syncthreads();

            // ---- 8x8 register-blocked FMA ----
            #pragma unroll
            for (int k = 0; k < BK; k++) {
                float a[TM], b[TN];
                *reinterpret_cast<float4*>(&a[0]) =
                    *reinterpret_cast<const float4*>(&As[k][ty * TM]);
                *reinterpret_cast<float4*>(&a[4]) =
                    *reinterpret_cast<const float4*>(&As[k][ty * TM + 4]);
                *reinterpret_cast<float4*>(&b[0]) =
                    *reinterpret_cast<const float4*>(&Bs[k][tx * TN]);
                *reinterpret_cast<float4*>(&b[4]) =
                    *reinterpret_cast<const float4*>(&Bs[k][tx * TN + 4]);
                #pragma unroll
                for (int i = 0; i < TM; i++)
                    #pragma unroll
                    for (int j = 0; j < TN; j++)
                        acc[i][j] = fmaf(a[i], b[j], acc[i][j]);
            }
            __syncthreads();
        }

        // ---- Epilogue: bias + store, only rows in [s0, s1) ----
        float bj[TN];
        *reinterpret_cast<float4*>(&bj[0]) =
            *reinterpret_cast<const float4*>(&bias[(size_t)t * 128 + tx * TN]);
        *reinterpret_cast<float4*>(&bj[4]) =
            *reinterpret_cast<const float4*>(&bias[(size_t)t * 128 + tx * TN + 4]);

        #pragma unroll
        for (int i = 0; i < TM; i++) {
            int m = ty * TM + i;
            if (m >= s0 && m < s1) {
                float4 v0, v1;
                v0.x = acc[i][0] + bj[0]; v0.y = acc[i][1] + bj[1];
                v0.z = acc[i][2] + bj[2]; v0.w = acc[i][3] + bj[3];
                v1.x = acc[i][4] + bj[4]; v1.y = acc[i][5] + bj[5];
                v1.z = acc[i][6] + bj[6]; v1.w = acc[i][7] + bj[7];
                float* o = &out[(size_t)(r0 + m) * 128 + tx * TN];
                *reinterpret_cast<float4*>(o)     = v0;
                *reinterpret_cast<float4*>(o + 4) = v1;
            }
        }

        s0 = s1;
    }
}

extern "C" void kernel_launch(void* const* d_in, const int* in_sizes, int n_in,
                              void* d_out, int out_size)
{
    const float* x   = (const float*)d_in[0];   // [N, 128]
    const int*   tv  = (const int*)  d_in[1];   // [N]
    const float* w   = (const float*)d_in[2];   // [16, 128, 128]
    const float* b   = (const float*)d_in[3];   // [16, 128]
    float*       out = (float*)d_out;           // [N, 128]

    const int N = in_sizes[1];                  // row count from type_vec
    const int grid = (N + BM - 1) / BM;         // 1024 for N=131072

    hetero_linear_kernel<<<grid, NTHREADS>>>(x, tv, w, b, out, N);
}

// round 3
// speedup vs baseline: 1.0018x; 1.0018x over previous
#include <cuda_runtime.h>

// ToHeteroLinear: out[i] = x[i] @ W[type[i]] + b[type[i]]
// N=131072, T=16, D_IN=D_OUT=128, fp32. type_vec is SORTED.
//
// Strategy: 128x128 output tile per block. Since types are sorted, almost all
// tiles are single-type -> plain register-blocked SGEMM vs W[t]. Tiles that
// straddle a type boundary (<= 15 of 1024) re-run the GEMM per segment and
// write only the segment's rows.

#define BM 128
#define BN 128
#define BK 32
#define TM 8
#define TN 8
#define NTHREADS 256   // (BM/TM)*(BN/TN)

__global__ __launch_bounds__(NTHREADS, 2)
void hetero_linear_kernel(const float* __restrict__ x,
                          const int* __restrict__ type_vec,
                          const float* __restrict__ weight,
                          const float* __restrict__ bias,
                          float* __restrict__ out,
                          int n_rows)
{
    __shared__ __align__(16) float As[BK][BM + 4];  // x tile, k-major (pad vs conflicts)
    __shared__ __align__(16) float Bs[BK][BN];      // W tile, k-major (natural layout)
    __shared__ int s_types[BM];

    const int r0  = blockIdx.x * BM;
    const int tid = threadIdx.x;

    // Stage the tile's type ids (sorted).
    if (tid < BM) {
        int r = r0 + tid;
        s_types[tid] = (r < n_rows) ? type_vec[r] : -1;
    }
    __syncthreads();

    const int tx = tid & 15;   // output-column group
    const int ty = tid >> 4;   // output-row group

    // Iterate contiguous same-type segments within the 128-row tile.
    // The scan is uniform across all threads (reads smem only), so the
    // __syncthreads() inside the loop body is safe.
    int s0 = 0;
    while (s0 < BM) {
        const int t = s_types[s0];
        int s1 = s0 + 1;
        while (s1 < BM && s_types[s1] == t) s1++;
        if (t < 0) break;  // tail guard (not hit: N % 128 == 0)

        const float* __restrict__ W = weight + (size_t)t * (128 * 128);

        float acc[TM][TN];
        #pragma unroll
        for (int i = 0; i < TM; i++)
            #pragma unroll
            for (int j = 0; j < TN; j++)
                acc[i][j] = 0.0f;

        // ---- Mainloop over K in chunks of BK=32 ----
        #pragma unroll
        for (int kt = 0; kt < 128; kt += BK) {
            // Load x tile [BM rows][BK cols] -> As[k][m] (transposed store).
            // 1024 float4 total, 4 per thread, coalesced global reads.
            #pragma unroll
            for (int it = 0; it < 4; it++) {
                int idx = tid + it * NTHREADS;      // 0..1023
                int m   = idx >> 3;                 // row in tile (0..127)
                int k4  = (idx & 7) << 2;           // k offset (0,4,..,28)
                float4 v = *reinterpret_cast<const float4*>(
                    &x[(size_t)(r0 + m) * 128 + kt + k4]);
                As[k4 + 0][m] = v.x;
                As[k4 + 1][m] = v.y;
                As[k4 + 2][m] = v.z;
                As[k4 + 3][m] = v.w;
            }
            // Load W tile [BK rows][BN cols] -> Bs (direct, coalesced float4).
            #pragma unroll
            for (int it = 0; it < 4; it++) {
                int idx = tid + it * NTHREADS;      // 0..1023
                int k   = idx >> 5;                 // 0..31
                int n4  = (idx & 31) << 2;          // 0,4,...,124
                *reinterpret_cast<float4*>(&Bs[k][n4]) =
                    *reinterpret_cast<const float4*>(&W[(size_t)(kt + k) * 128 + n4]);
            }
            __syncthreads();

            // ---- 8x8 register-blocked FMA ----
            #pragma unroll
            for (int k = 0; k < BK; k++) {
                float a[TM], b[TN];
                *reinterpret_cast<float4*>(&a[0]) =
                    *reinterpret_cast<const float4*>(&As[k][ty * TM]);
                *reinterpret_cast<float4*>(&a[4]) =
                    *reinterpret_cast<const float4*>(&As[k][ty * TM + 4]);
                *reinterpret_cast<float4*>(&b[0]) =
                    *reinterpret_cast<const float4*>(&Bs[k][tx * TN]);
                *reinterpret_cast<float4*>(&b[4]) =
                    *reinterpret_cast<const float4*>(&Bs[k][tx * TN + 4]);
                #pragma unroll
                for (int i = 0; i < TM; i++)
                    #pragma unroll
                    for (int j = 0; j < TN; j++)
                        acc[i][j] = fmaf(a[i], b[j], acc[i][j]);
            }
            __syncthreads();
        }

        // ---- Epilogue: bias + store, only rows in [s0, s1) ----
        float bj[TN];
        *reinterpret_cast<float4*>(&bj[0]) =
            *reinterpret_cast<const float4*>(&bias[(size_t)t * 128 + tx * TN]);
        *reinterpret_cast<float4*>(&bj[4]) =
            *reinterpret_cast<const float4*>(&bias[(size_t)t * 128 + tx * TN + 4]);

        #pragma unroll
        for (int i = 0; i < TM; i++) {
            int m = ty * TM + i;
            if (m >= s0 && m < s1) {
                float4 v0, v1;
                v0.x = acc[i][0] + bj[0]; v0.y = acc[i][1] + bj[1];
                v0.z = acc[i][2] + bj[2]; v0.w = acc[i][3] + bj[3];
                v1.x = acc[i][4] + bj[4]; v1.y = acc[i][5] + bj[5];
                v1.z = acc[i][6] + bj[6]; v1.w = acc[i][7] + bj[7];
                float* o = &out[(size_t)(r0 + m) * 128 + tx * TN];
                *reinterpret_cast<float4*>(o)     = v0;
                *reinterpret_cast<float4*>(o + 4) = v1;
            }
        }

        s0 = s1;
    }
}

extern "C" void kernel_launch(void* const* d_in, const int* in_sizes, int n_in,
                              void* d_out, int out_size)
{
    const float* x   = (const float*)d_in[0];   // [N, 128]
    const int*   tv  = (const int*)  d_in[1];   // [N]
    const float* w   = (const float*)d_in[2];   // [16, 128, 128]
    const float* b   = (const float*)d_in[3];   // [16, 128]
    float*       out = (float*)d_out;           // [N, 128]

    const int N = in_sizes[1];                  // row count from type_vec
    const int grid = (N + BM - 1) / BM;         // 1024 for N=131072

    hetero_linear_kernel<<<grid, NTHREADS>>>(x, tv, w, b, out, N);
}